// round 2
// baseline (speedup 1.0000x reference)
#include <cuda_runtime.h>

#define N_ATOMS 50000
#define N_EDGES 1600000
#define NF      128
#define NRBF    20
#define TSTRIDE 130   // padded row stride for shared tiles (conflict-free a-loads)

// Intermediate buffers (no allocation allowed -> device globals)
__device__ float g_h[(size_t)N_ATOMS * NF];
__device__ float g_y[(size_t)N_ATOMS * NF];

__device__ __forceinline__ float sspf(float v) {
    // shifted softplus: log(1+e^x) - log(2), numerically stable
    return fmaxf(v, 0.f) + log1pf(__expf(-fabsf(v))) - 0.6931471805599453f;
}

// ---------------------------------------------------------------------------
// zero g_y
// ---------------------------------------------------------------------------
__global__ void zero_y_kernel() {
    const int n4 = N_ATOMS * NF / 4;
    float4 z = make_float4(0.f, 0.f, 0.f, 0.f);
    for (int i = blockIdx.x * blockDim.x + threadIdx.x; i < n4;
         i += gridDim.x * blockDim.x)
        reinterpret_cast<float4*>(g_y)[i] = z;
}

// ---------------------------------------------------------------------------
// h = x @ W_in2f      (tile: 128 rows x 128 cols, K=128)
// ---------------------------------------------------------------------------
__global__ void __launch_bounds__(256, 1)
h_kernel(const float* __restrict__ x, const float* __restrict__ W) {
    extern __shared__ float sm[];
    float* sx = sm;                   // 128*TSTRIDE
    float* sW = sm + 128 * TSTRIDE;   // 128*128

    const int tid = threadIdx.x;
    const int tx = tid & 15, ty = tid >> 4;
    const int c0 = tx * 8, r0 = ty * 8;
    const int rbase = blockIdx.x * 128;

    for (int i = tid; i < 128 * 32; i += 256)
        reinterpret_cast<float4*>(sW)[i] = reinterpret_cast<const float4*>(W)[i];
    for (int i = tid; i < 128 * 32; i += 256) {
        int r = i >> 5, c4 = (i & 31) * 4;
        float4 v = make_float4(0.f, 0.f, 0.f, 0.f);
        if (rbase + r < N_ATOMS)
            v = reinterpret_cast<const float4*>(x)[(size_t)(rbase + r) * 32 + (i & 31)];
        float* d = &sx[r * TSTRIDE + c4];
        d[0] = v.x; d[1] = v.y; d[2] = v.z; d[3] = v.w;
    }
    __syncthreads();

    float acc[8][8];
#pragma unroll
    for (int i = 0; i < 8; i++)
#pragma unroll
        for (int j = 0; j < 8; j++) acc[i][j] = 0.f;

    for (int k = 0; k < 128; k++) {
        float a[8];
#pragma unroll
        for (int i = 0; i < 8; i++) a[i] = sx[(r0 + i) * TSTRIDE + k];
        float4 w0 = *reinterpret_cast<const float4*>(&sW[k * 128 + c0]);
        float4 w1 = *reinterpret_cast<const float4*>(&sW[k * 128 + c0 + 4]);
        float w[8] = {w0.x, w0.y, w0.z, w0.w, w1.x, w1.y, w1.z, w1.w};
#pragma unroll
        for (int i = 0; i < 8; i++)
#pragma unroll
            for (int j = 0; j < 8; j++) acc[i][j] = fmaf(a[i], w[j], acc[i][j]);
    }

#pragma unroll
    for (int i = 0; i < 8; i++) {
        int r = rbase + r0 + i;
        if (r < N_ATOMS) {
            float4 o0 = make_float4(acc[i][0], acc[i][1], acc[i][2], acc[i][3]);
            float4 o1 = make_float4(acc[i][4], acc[i][5], acc[i][6], acc[i][7]);
            float4* dst = reinterpret_cast<float4*>(&g_h[(size_t)r * 128 + c0]);
            dst[0] = o0; dst[1] = o1;
        }
    }
}

// ---------------------------------------------------------------------------
// Edge kernel: Wij = (ssp(f@W1+b1)@W2 + b2) * rcut;
//              y[idx_i] += h[idx_j] * Wij   (idx_i sorted -> run accumulate)
// ---------------------------------------------------------------------------
__global__ void __launch_bounds__(256, 1)
edge_kernel(const float* __restrict__ f_ij, const float* __restrict__ rcut,
            const int* __restrict__ idx_i, const int* __restrict__ idx_j,
            const float* __restrict__ W1, const float* __restrict__ b1,
            const float* __restrict__ W2, const float* __restrict__ b2) {
    extern __shared__ float sm[];
    float* sW1 = sm;             // 20*128   = 2560
    float* sW2 = sW1 + 2560;     // 128*128  = 16384
    float* sf  = sW2 + 16384;    // 128*20   = 2560
    float* st  = sf + 2560;      // 128*TSTRIDE = 16640
    float* sb1 = st + 16640;     // 128
    float* sb2 = sb1 + 128;      // 128
    float* src = sb2 + 128;      // 128
    int*   sii = (int*)(src + 128);  // 128
    int*   sjj = sii + 128;          // 128

    const int tid = threadIdx.x;
    const int tx = tid & 15, ty = tid >> 4;
    const int c0 = tx * 8, e0 = ty * 8;
    const int ebase = blockIdx.x * 128;

    for (int i = tid; i < 640; i += 256)
        reinterpret_cast<float4*>(sW1)[i] = reinterpret_cast<const float4*>(W1)[i];
    for (int i = tid; i < 4096; i += 256)
        reinterpret_cast<float4*>(sW2)[i] = reinterpret_cast<const float4*>(W2)[i];
    for (int i = tid; i < 640; i += 256)
        reinterpret_cast<float4*>(sf)[i] =
            reinterpret_cast<const float4*>(f_ij + (size_t)ebase * NRBF)[i];
    if (tid < 128) {
        sb1[tid] = b1[tid];
        sb2[tid] = b2[tid];
        src[tid] = rcut[ebase + tid];
        sii[tid] = idx_i[ebase + tid];
        sjj[tid] = idx_j[ebase + tid];
    }
    __syncthreads();

    // GEMM1: t = ssp(f @ W1 + b1), K = 20
    {
        float acc[8][8];
#pragma unroll
        for (int i = 0; i < 8; i++)
#pragma unroll
            for (int j = 0; j < 8; j++) acc[i][j] = 0.f;

#pragma unroll
        for (int k = 0; k < NRBF; k++) {
            float a[8];
#pragma unroll
            for (int i = 0; i < 8; i++) a[i] = sf[(e0 + i) * NRBF + k];
            float4 w0 = *reinterpret_cast<const float4*>(&sW1[k * 128 + c0]);
            float4 w1 = *reinterpret_cast<const float4*>(&sW1[k * 128 + c0 + 4]);
            float w[8] = {w0.x, w0.y, w0.z, w0.w, w1.x, w1.y, w1.z, w1.w};
#pragma unroll
            for (int i = 0; i < 8; i++)
#pragma unroll
                for (int j = 0; j < 8; j++) acc[i][j] = fmaf(a[i], w[j], acc[i][j]);
        }
#pragma unroll
        for (int i = 0; i < 8; i++)
#pragma unroll
            for (int j = 0; j < 8; j++)
                st[(e0 + i) * TSTRIDE + c0 + j] = sspf(acc[i][j] + sb1[c0 + j]);
    }
    __syncthreads();

    // GEMM2: Wij_pre = t @ W2, K = 128
    float acc[8][8];
#pragma unroll
    for (int i = 0; i < 8; i++)
#pragma unroll
        for (int j = 0; j < 8; j++) acc[i][j] = 0.f;

    for (int k = 0; k < 128; k++) {
        float a[8];
#pragma unroll
        for (int i = 0; i < 8; i++) a[i] = st[(e0 + i) * TSTRIDE + k];
        float4 w0 = *reinterpret_cast<const float4*>(&sW2[k * 128 + c0]);
        float4 w1 = *reinterpret_cast<const float4*>(&sW2[k * 128 + c0 + 4]);
        float w[8] = {w0.x, w0.y, w0.z, w0.w, w1.x, w1.y, w1.z, w1.w};
#pragma unroll
        for (int i = 0; i < 8; i++)
#pragma unroll
            for (int j = 0; j < 8; j++) acc[i][j] = fmaf(a[i], w[j], acc[i][j]);
    }

    // Epilogue: gather h[idx_j], modulate, run-accumulate into g_y (idx_i sorted)
    float bias[8];
#pragma unroll
    for (int j = 0; j < 8; j++) bias[j] = sb2[c0 + j];

    float run[8];
    int cur = -1;
#pragma unroll
    for (int i = 0; i < 8; i++) {
        const int e = e0 + i;
        const int ii = sii[e];
        if (ii != cur) {
            if (cur >= 0) {
#pragma unroll
                for (int j = 0; j < 8; j++)
                    atomicAdd(&g_y[(size_t)cur * 128 + c0 + j], run[j]);
            }
            cur = ii;
#pragma unroll
            for (int j = 0; j < 8; j++) run[j] = 0.f;
        }
        const float r = src[e];
        const float4* hp =
            reinterpret_cast<const float4*>(&g_h[(size_t)sjj[e] * 128 + c0]);
        float4 h0 = hp[0], h1 = hp[1];
        float hv[8] = {h0.x, h0.y, h0.z, h0.w, h1.x, h1.y, h1.z, h1.w};
#pragma unroll
        for (int j = 0; j < 8; j++)
            run[j] = fmaf((acc[i][j] + bias[j]) * r, hv[j], run[j]);
    }
#pragma unroll
    for (int j = 0; j < 8; j++)
        atomicAdd(&g_y[(size_t)cur * 128 + c0 + j], run[j]);
}

// ---------------------------------------------------------------------------
// out = ssp(y @ W_o1 + b_o1) @ W_o2 + b_o2
// ---------------------------------------------------------------------------
__global__ void __launch_bounds__(256, 1)
out_kernel(const float* __restrict__ Wo1, const float* __restrict__ bo1,
           const float* __restrict__ Wo2, const float* __restrict__ bo2,
           float* __restrict__ out) {
    extern __shared__ float sm[];
    float* sy = sm;                   // 128*TSTRIDE (reused as t after phase 1)
    float* sW = sm + 128 * TSTRIDE;   // 128*128
    float* sb = sW + 16384;           // 128

    const int tid = threadIdx.x;
    const int tx = tid & 15, ty = tid >> 4;
    const int c0 = tx * 8, r0 = ty * 8;
    const int rbase = blockIdx.x * 128;

    for (int i = tid; i < 4096; i += 256)
        reinterpret_cast<float4*>(sW)[i] = reinterpret_cast<const float4*>(Wo1)[i];
    if (tid < 128) sb[tid] = bo1[tid];
    for (int i = tid; i < 128 * 32; i += 256) {
        int r = i >> 5, c4 = (i & 31) * 4;
        float4 v = make_float4(0.f, 0.f, 0.f, 0.f);
        if (rbase + r < N_ATOMS)
            v = reinterpret_cast<const float4*>(g_y)[(size_t)(rbase + r) * 32 + (i & 31)];
        float* d = &sy[r * TSTRIDE + c4];
        d[0] = v.x; d[1] = v.y; d[2] = v.z; d[3] = v.w;
    }
    __syncthreads();

    // GEMM1
    float acc[8][8];
#pragma unroll
    for (int i = 0; i < 8; i++)
#pragma unroll
        for (int j = 0; j < 8; j++) acc[i][j] = 0.f;

    for (int k = 0; k < 128; k++) {
        float a[8];
#pragma unroll
        for (int i = 0; i < 8; i++) a[i] = sy[(r0 + i) * TSTRIDE + k];
        float4 w0 = *reinterpret_cast<const float4*>(&sW[k * 128 + c0]);
        float4 w1 = *reinterpret_cast<const float4*>(&sW[k * 128 + c0 + 4]);
        float w[8] = {w0.x, w0.y, w0.z, w0.w, w1.x, w1.y, w1.z, w1.w};
#pragma unroll
        for (int i = 0; i < 8; i++)
#pragma unroll
            for (int j = 0; j < 8; j++) acc[i][j] = fmaf(a[i], w[j], acc[i][j]);
    }
    __syncthreads();   // all reads of sy / sW / sb(bo1) complete

    // ssp + bias -> store t into sy's buffer
#pragma unroll
    for (int i = 0; i < 8; i++)
#pragma unroll
        for (int j = 0; j < 8; j++)
            sy[(r0 + i) * TSTRIDE + c0 + j] = sspf(acc[i][j] + sb[c0 + j]);
    __syncthreads();

    // load second layer weights
    for (int i = tid; i < 4096; i += 256)
        reinterpret_cast<float4*>(sW)[i] = reinterpret_cast<const float4*>(Wo2)[i];
    if (tid < 128) sb[tid] = bo2[tid];
    __syncthreads();

    // GEMM2
    float acc2[8][8];
#pragma unroll
    for (int i = 0; i < 8; i++)
#pragma unroll
        for (int j = 0; j < 8; j++) acc2[i][j] = 0.f;

    for (int k = 0; k < 128; k++) {
        float a[8];
#pragma unroll
        for (int i = 0; i < 8; i++) a[i] = sy[(r0 + i) * TSTRIDE + k];
        float4 w0 = *reinterpret_cast<const float4*>(&sW[k * 128 + c0]);
        float4 w1 = *reinterpret_cast<const float4*>(&sW[k * 128 + c0 + 4]);
        float w[8] = {w0.x, w0.y, w0.z, w0.w, w1.x, w1.y, w1.z, w1.w};
#pragma unroll
        for (int i = 0; i < 8; i++)
#pragma unroll
            for (int j = 0; j < 8; j++) acc2[i][j] = fmaf(a[i], w[j], acc2[i][j]);
    }

#pragma unroll
    for (int i = 0; i < 8; i++) {
        int r = rbase + r0 + i;
        if (r < N_ATOMS) {
            float4 o0 = make_float4(acc2[i][0] + sb[c0 + 0], acc2[i][1] + sb[c0 + 1],
                                    acc2[i][2] + sb[c0 + 2], acc2[i][3] + sb[c0 + 3]);
            float4 o1 = make_float4(acc2[i][4] + sb[c0 + 4], acc2[i][5] + sb[c0 + 5],
                                    acc2[i][6] + sb[c0 + 6], acc2[i][7] + sb[c0 + 7]);
            float4* dst = reinterpret_cast<float4*>(&out[(size_t)r * 128 + c0]);
            dst[0] = o0; dst[1] = o1;
        }
    }
}

// ---------------------------------------------------------------------------
extern "C" void kernel_launch(void* const* d_in, const int* in_sizes, int n_in,
                              void* d_out, int out_size) {
    const float* x      = (const float*)d_in[0];
    const float* f_ij   = (const float*)d_in[1];
    const float* rcut   = (const float*)d_in[2];
    const int*   idx_i  = (const int*)d_in[3];
    const int*   idx_j  = (const int*)d_in[4];
    const float* W_in2f = (const float*)d_in[5];
    const float* W_f1   = (const float*)d_in[6];
    const float* b_f1   = (const float*)d_in[7];
    const float* W_f2   = (const float*)d_in[8];
    const float* b_f2   = (const float*)d_in[9];
    const float* W_o1   = (const float*)d_in[10];
    const float* b_o1   = (const float*)d_in[11];
    const float* W_o2   = (const float*)d_in[12];
    const float* b_o2   = (const float*)d_in[13];
    float* out = (float*)d_out;

    const int smemA = (128 * TSTRIDE + 128 * 128) * 4;
    const int smemB = (2560 + 16384 + 2560 + 16640 + 3 * 128 + 2 * 128) * 4;
    const int smemC = (128 * TSTRIDE + 128 * 128 + 128) * 4;

    cudaFuncSetAttribute(h_kernel, cudaFuncAttributeMaxDynamicSharedMemorySize, smemA);
    cudaFuncSetAttribute(edge_kernel, cudaFuncAttributeMaxDynamicSharedMemorySize, smemB);
    cudaFuncSetAttribute(out_kernel, cudaFuncAttributeMaxDynamicSharedMemorySize, smemC);

    zero_y_kernel<<<512, 256>>>();
    h_kernel<<<(N_ATOMS + 127) / 128, 256, smemA>>>(x, W_in2f);
    edge_kernel<<<N_EDGES / 128, 256, smemB>>>(f_ij, rcut, idx_i, idx_j,
                                               W_f1, b_f1, W_f2, b_f2);
    out_kernel<<<(N_ATOMS + 127) / 128, 256, smemC>>>(W_o1, b_o1, W_o2, b_o2, out);
}

// round 4
// speedup vs baseline: 1.6196x; 1.6196x over previous
#include <cuda_runtime.h>
#include <cuda_bf16.h>
#include <cstdint>

#define N_ATOMS 50000
#define N_EDGES 1600000
#define NF      128
#define NRBF    20
#define TSTRIDE 130

// A/B bf16 tile row stride in elements (128 data + 8 pad -> 272B rows,
// conflict-free ldmatrix: 272/4 = 68 = 4 mod 32 -> 8 rows hit 8 distinct
// 4-bank groups)
#define KSTR 136
#define BTILE_BYTES (128 * KSTR * 2)   // 34816

// ---------------- device globals (no allocation allowed) -------------------
__device__ float g_h[(size_t)N_ATOMS * NF];
__device__ float g_y[(size_t)N_ATOMS * NF];
// W2^T ([n][k], stride KSTR) hi/lo bf16 byte images (zero-init padding)
__device__ __align__(16) unsigned char g_Bhi[BTILE_BYTES];
__device__ __align__(16) unsigned char g_Blo[BTILE_BYTES];

__device__ __forceinline__ float sspf(float v) {
    return fmaxf(v, 0.f) + log1pf(__expf(-fabsf(v))) - 0.6931471805599453f;
}

__device__ __forceinline__ uint32_t smem_u32(const void* p) {
    uint32_t a;
    asm("{ .reg .u64 t; cvta.to.shared.u64 t, %1; cvt.u32.u64 %0, t; }" : "=r"(a) : "l"(p));
    return a;
}

__device__ __forceinline__ void ldsm_x4(uint32_t addr, uint32_t r[4]) {
    asm volatile("ldmatrix.sync.aligned.m8n8.x4.shared.b16 {%0,%1,%2,%3}, [%4];"
                 : "=r"(r[0]), "=r"(r[1]), "=r"(r[2]), "=r"(r[3]) : "r"(addr));
}

__device__ __forceinline__ void mma_bf16(float c[4], const uint32_t a[4],
                                         uint32_t b0, uint32_t b1) {
    asm volatile(
        "mma.sync.aligned.m16n8k16.row.col.f32.bf16.bf16.f32 "
        "{%0,%1,%2,%3}, {%4,%5,%6,%7}, {%8,%9}, {%0,%1,%2,%3};"
        : "+f"(c[0]), "+f"(c[1]), "+f"(c[2]), "+f"(c[3])
        : "r"(a[0]), "r"(a[1]), "r"(a[2]), "r"(a[3]), "r"(b0), "r"(b1));
}

// ---------------------------------------------------------------------------
// prep: W2 [k][n] -> W2^T [n][k] hi/lo bf16, stride KSTR
// ---------------------------------------------------------------------------
__global__ void prep_w2_kernel(const float* __restrict__ W2) {
    int i = blockIdx.x * blockDim.x + threadIdx.x;
    if (i >= 16384) return;
    int k = i >> 7, n = i & 127;
    float v = W2[k * 128 + n];
    __nv_bfloat16 hi = __float2bfloat16(v);
    __nv_bfloat16 lo = __float2bfloat16(v - __bfloat162float(hi));
    uint32_t off = (uint32_t)n * (KSTR * 2) + (uint32_t)k * 2;
    *(__nv_bfloat16*)(g_Bhi + off) = hi;
    *(__nv_bfloat16*)(g_Blo + off) = lo;
}

__global__ void zero_y_kernel() {
    const int n4 = N_ATOMS * NF / 4;
    float4 z = make_float4(0.f, 0.f, 0.f, 0.f);
    for (int i = blockIdx.x * blockDim.x + threadIdx.x; i < n4;
         i += gridDim.x * blockDim.x)
        reinterpret_cast<float4*>(g_y)[i] = z;
}

// ---------------------------------------------------------------------------
// h = x @ W_in2f
// ---------------------------------------------------------------------------
__global__ void __launch_bounds__(256, 1)
h_kernel(const float* __restrict__ x, const float* __restrict__ W) {
    extern __shared__ float sm[];
    float* sx = sm;
    float* sW = sm + 128 * TSTRIDE;

    const int tid = threadIdx.x;
    const int tx = tid & 15, ty = tid >> 4;
    const int c0 = tx * 8, r0 = ty * 8;
    const int rbase = blockIdx.x * 128;

    for (int i = tid; i < 128 * 32; i += 256)
        reinterpret_cast<float4*>(sW)[i] = reinterpret_cast<const float4*>(W)[i];
    for (int i = tid; i < 128 * 32; i += 256) {
        int r = i >> 5, c4 = (i & 31) * 4;
        float4 v = make_float4(0.f, 0.f, 0.f, 0.f);
        if (rbase + r < N_ATOMS)
            v = reinterpret_cast<const float4*>(x)[(size_t)(rbase + r) * 32 + (i & 31)];
        float* d = &sx[r * TSTRIDE + c4];
        d[0] = v.x; d[1] = v.y; d[2] = v.z; d[3] = v.w;
    }
    __syncthreads();

    float acc[8][8];
#pragma unroll
    for (int i = 0; i < 8; i++)
#pragma unroll
        for (int j = 0; j < 8; j++) acc[i][j] = 0.f;

    for (int k = 0; k < 128; k++) {
        float a[8];
#pragma unroll
        for (int i = 0; i < 8; i++) a[i] = sx[(r0 + i) * TSTRIDE + k];
        float4 w0 = *reinterpret_cast<const float4*>(&sW[k * 128 + c0]);
        float4 w1 = *reinterpret_cast<const float4*>(&sW[k * 128 + c0 + 4]);
        float w[8] = {w0.x, w0.y, w0.z, w0.w, w1.x, w1.y, w1.z, w1.w};
#pragma unroll
        for (int i = 0; i < 8; i++)
#pragma unroll
            for (int j = 0; j < 8; j++) acc[i][j] = fmaf(a[i], w[j], acc[i][j]);
    }

#pragma unroll
    for (int i = 0; i < 8; i++) {
        int r = rbase + r0 + i;
        if (r < N_ATOMS) {
            float4 o0 = make_float4(acc[i][0], acc[i][1], acc[i][2], acc[i][3]);
            float4 o1 = make_float4(acc[i][4], acc[i][5], acc[i][6], acc[i][7]);
            float4* dst = reinterpret_cast<float4*>(&g_h[(size_t)r * 128 + c0]);
            dst[0] = o0; dst[1] = o1;
        }
    }
}

// ---------------------------------------------------------------------------
// Edge kernel: GEMM2 on mma.sync bf16 (3-term hi/lo split)
// smem layout (bytes):
//   0      : B_hi  (34816)
//   34816  : B_lo  (34816)
//   69632  : A_hi  (34816)  \  aliased by st (128*132 f32 = 67584B) after MMA
//   104448 : A_lo  (34816)  /
//   139264 : sW1   (10240)
//   149504 : sf    (10240)
//   159744 : sb1/sb2/src/sii/sjj (5 x 512)
// ---------------------------------------------------------------------------
#define OFF_BHI  0
#define OFF_BLO  34816
#define OFF_AHI  69632
#define OFF_ALO  104448
#define OFF_ST   69632
#define OFF_W1   139264
#define OFF_F    149504
#define OFF_B1   159744
#define OFF_B2   160256
#define OFF_RC   160768
#define OFF_II   161280
#define OFF_JJ   161792
#define SMEM_EDGE 162304
#define STSTR 132

__global__ void __launch_bounds__(256, 1)
edge_kernel(const float* __restrict__ f_ij, const float* __restrict__ rcut,
            const int* __restrict__ idx_i, const int* __restrict__ idx_j,
            const float* __restrict__ W1, const float* __restrict__ b1,
            const float* __restrict__ b2) {
    extern __shared__ __align__(16) unsigned char smraw[];
    const int tid = threadIdx.x;
    const int wid = tid >> 5, lane = tid & 31;
    const uint32_t sbase = smem_u32(smraw);
    const int ebase = blockIdx.x * 128;

    float* sW1 = (float*)(smraw + OFF_W1);
    float* sf  = (float*)(smraw + OFF_F);
    float* sb1 = (float*)(smraw + OFF_B1);
    float* sb2 = (float*)(smraw + OFF_B2);
    float* src = (float*)(smraw + OFF_RC);
    int*   sii = (int*)(smraw + OFF_II);
    int*   sjj = (int*)(smraw + OFF_JJ);

    // stage W2^T hi/lo images + per-tile inputs
    {
        uint4* d1 = (uint4*)(smraw + OFF_BHI);
        uint4* d2 = (uint4*)(smraw + OFF_BLO);
        const uint4* s1 = (const uint4*)g_Bhi;
        const uint4* s2 = (const uint4*)g_Blo;
        for (int i = tid; i < BTILE_BYTES / 16; i += 256) { d1[i] = s1[i]; d2[i] = s2[i]; }
        for (int i = tid; i < 640; i += 256)
            ((float4*)sW1)[i] = ((const float4*)W1)[i];
        for (int i = tid; i < 640; i += 256)
            ((float4*)sf)[i] = ((const float4*)(f_ij + (size_t)ebase * NRBF))[i];
        if (tid < 128) {
            sb1[tid] = b1[tid];
            sb2[tid] = b2[tid];
            src[tid] = rcut[ebase + tid];
            sii[tid] = idx_i[ebase + tid];
            sjj[tid] = idx_j[ebase + tid];
        }
    }
    __syncthreads();

    // ---- GEMM1 (FFMA): t = ssp(f @ W1 + b1) -> bf16 hi/lo into A tiles
    {
        const int tx = tid & 15, ty = tid >> 4;
        const int c0 = tx * 8, e0 = ty * 8;
        float acc[8][8];
#pragma unroll
        for (int i = 0; i < 8; i++)
#pragma unroll
            for (int j = 0; j < 8; j++) acc[i][j] = 0.f;

#pragma unroll
        for (int k = 0; k < NRBF; k++) {
            float a[8];
#pragma unroll
            for (int i = 0; i < 8; i++) a[i] = sf[(e0 + i) * NRBF + k];
            float4 w0 = *(const float4*)(&sW1[k * 128 + c0]);
            float4 w1 = *(const float4*)(&sW1[k * 128 + c0 + 4]);
            float w[8] = {w0.x, w0.y, w0.z, w0.w, w1.x, w1.y, w1.z, w1.w};
#pragma unroll
            for (int i = 0; i < 8; i++)
#pragma unroll
                for (int j = 0; j < 8; j++) acc[i][j] = fmaf(a[i], w[j], acc[i][j]);
        }

#pragma unroll
        for (int i = 0; i < 8; i++) {
            uint32_t hi4[4], lo4[4];
#pragma unroll
            for (int j = 0; j < 4; j++) {
                float t0 = sspf(acc[i][2 * j]     + sb1[c0 + 2 * j]);
                float t1 = sspf(acc[i][2 * j + 1] + sb1[c0 + 2 * j + 1]);
                __nv_bfloat16 h0 = __float2bfloat16(t0);
                __nv_bfloat16 h1 = __float2bfloat16(t1);
                __nv_bfloat16 l0 = __float2bfloat16(t0 - __bfloat162float(h0));
                __nv_bfloat16 l1 = __float2bfloat16(t1 - __bfloat162float(h1));
                hi4[j] = ((uint32_t)*(uint16_t*)&h1 << 16) | *(uint16_t*)&h0;
                lo4[j] = ((uint32_t)*(uint16_t*)&l1 << 16) | *(uint16_t*)&l0;
            }
            uint32_t off = (uint32_t)(e0 + i) * (KSTR * 2) + (uint32_t)c0 * 2;
            *(uint4*)(smraw + OFF_AHI + off) = make_uint4(hi4[0], hi4[1], hi4[2], hi4[3]);
            *(uint4*)(smraw + OFF_ALO + off) = make_uint4(lo4[0], lo4[1], lo4[2], lo4[3]);
        }
    }
    __syncthreads();

    // ---- GEMM2: warp w owns edges m0 = 16w .. 16w+15, all 128 cols.
    float acc[16][4];
#pragma unroll
    for (int t = 0; t < 16; t++)
#pragma unroll
        for (int j = 0; j < 4; j++) acc[t][j] = 0.f;

    {
        const int m0 = wid * 16;
        // ldmatrix lane address components
        const int arow = m0 + (lane & 15);
        const int koff = (lane >> 4) << 3;          // 0 or 8
        const uint32_t a_hi_base = sbase + OFF_AHI + (uint32_t)arow * (KSTR * 2);
        const uint32_t a_lo_base = sbase + OFF_ALO + (uint32_t)arow * (KSTR * 2);

#pragma unroll
        for (int kk = 0; kk < 8; kk++) {
            const int k0 = kk * 16;
            uint32_t ah[4], al[4];
            ldsm_x4(a_hi_base + (uint32_t)(k0 + koff) * 2, ah);
            ldsm_x4(a_lo_base + (uint32_t)(k0 + koff) * 2, al);

#pragma unroll
            for (int ntp = 0; ntp < 8; ntp++) {
                const int nrow = ntp * 16 + (lane & 15);
                const uint32_t baddr =
                    (uint32_t)nrow * (KSTR * 2) + (uint32_t)(k0 + koff) * 2;
                uint32_t bh[4], bl[4];
                ldsm_x4(sbase + OFF_BHI + baddr, bh);
                ldsm_x4(sbase + OFF_BLO + baddr, bl);
                // n-tile 2*ntp uses {r0, r2}; 2*ntp+1 uses {r1, r3}
                mma_bf16(acc[2 * ntp],     ah, bh[0], bh[2]);
                mma_bf16(acc[2 * ntp],     ah, bl[0], bl[2]);
                mma_bf16(acc[2 * ntp],     al, bh[0], bh[2]);
                mma_bf16(acc[2 * ntp + 1], ah, bh[1], bh[3]);
                mma_bf16(acc[2 * ntp + 1], ah, bl[1], bl[3]);
                mma_bf16(acc[2 * ntp + 1], al, bh[1], bh[3]);
            }
        }
    }
    __syncthreads();   // all warps done reading A/B before st aliases A

    // ---- epilogue: modulate + stage to st [128][STSTR] f32
    {
        const int m0 = wid * 16;
        const int row0 = m0 + (lane >> 2);
        const int row1 = row0 + 8;
        const int cb = (lane & 3);           // column sub-offset /2
        const float r0v = src[row0], r1v = src[row1];
        const int   j0 = sjj[row0],  j1 = sjj[row1];
        const float2* h0p = (const float2*)(g_h + (size_t)j0 * 128);
        const float2* h1p = (const float2*)(g_h + (size_t)j1 * 128);
        const float2* b2p = (const float2*)sb2;
        float2* st2 = (float2*)(smraw + OFF_ST);

#pragma unroll
        for (int nt = 0; nt < 16; nt++) {
            const int ci = nt * 4 + cb;      // float2 index (col = 2*ci)
            float2 bv = b2p[ci];
            float2 ha = h0p[ci];
            float2 hb = h1p[ci];
            float2 v0, v1;
            v0.x = (acc[nt][0] + bv.x) * r0v * ha.x;
            v0.y = (acc[nt][1] + bv.y) * r0v * ha.y;
            v1.x = (acc[nt][2] + bv.x) * r1v * hb.x;
            v1.y = (acc[nt][3] + bv.y) * r1v * hb.y;
            st2[row0 * (STSTR / 2) + ci] = v0;
            st2[row1 * (STSTR / 2) + ci] = v1;
        }
    }
    __syncthreads();

    // ---- run-accumulate scatter (idx_i sorted)
    {
        const int tx = tid & 15, ty = tid >> 4;
        const int e0 = ty * 8;
        const float* st = (const float*)(smraw + OFF_ST);
        float run0[4], run1[4];
        int cur = -1;
#pragma unroll
        for (int i = 0; i < 8; i++) {
            const int e = e0 + i;
            const int ii = sii[e];
            if (ii != cur) {
                if (cur >= 0) {
                    float* y0 = g_y + (size_t)cur * 128 + 4 * tx;
#pragma unroll
                    for (int j = 0; j < 4; j++) atomicAdd(y0 + j, run0[j]);
#pragma unroll
                    for (int j = 0; j < 4; j++) atomicAdd(y0 + 64 + j, run1[j]);
                }
                cur = ii;
#pragma unroll
                for (int j = 0; j < 4; j++) { run0[j] = 0.f; run1[j] = 0.f; }
            }
            float4 v0 = *(const float4*)(st + e * STSTR + 4 * tx);
            float4 v1 = *(const float4*)(st + e * STSTR + 64 + 4 * tx);
            run0[0] += v0.x; run0[1] += v0.y; run0[2] += v0.z; run0[3] += v0.w;
            run1[0] += v1.x; run1[1] += v1.y; run1[2] += v1.z; run1[3] += v1.w;
        }
        float* y0 = g_y + (size_t)cur * 128 + 4 * tx;
#pragma unroll
        for (int j = 0; j < 4; j++) atomicAdd(y0 + j, run0[j]);
#pragma unroll
        for (int j = 0; j < 4; j++) atomicAdd(y0 + 64 + j, run1[j]);
    }
}

// ---------------------------------------------------------------------------
// out = ssp(y @ W_o1 + b_o1) @ W_o2 + b_o2
// ---------------------------------------------------------------------------
__global__ void __launch_bounds__(256, 1)
out_kernel(const float* __restrict__ Wo1, const float* __restrict__ bo1,
           const float* __restrict__ Wo2, const float* __restrict__ bo2,
           float* __restrict__ out) {
    extern __shared__ float sm[];
    float* sy = sm;
    float* sW = sm + 128 * TSTRIDE;
    float* sb = sW + 16384;

    const int tid = threadIdx.x;
    const int tx = tid & 15, ty = tid >> 4;
    const int c0 = tx * 8, r0 = ty * 8;
    const int rbase = blockIdx.x * 128;

    for (int i = tid; i < 4096; i += 256)
        reinterpret_cast<float4*>(sW)[i] = reinterpret_cast<const float4*>(Wo1)[i];
    if (tid < 128) sb[tid] = bo1[tid];
    for (int i = tid; i < 128 * 32; i += 256) {
        int r = i >> 5, c4 = (i & 31) * 4;
        float4 v = make_float4(0.f, 0.f, 0.f, 0.f);
        if (rbase + r < N_ATOMS)
            v = reinterpret_cast<const float4*>(g_y)[(size_t)(rbase + r) * 32 + (i & 31)];
        float* d = &sy[r * TSTRIDE + c4];
        d[0] = v.x; d[1] = v.y; d[2] = v.z; d[3] = v.w;
    }
    __syncthreads();

    float acc[8][8];
#pragma unroll
    for (int i = 0; i < 8; i++)
#pragma unroll
        for (int j = 0; j < 8; j++) acc[i][j] = 0.f;

    for (int k = 0; k < 128; k++) {
        float a[8];
#pragma unroll
        for (int i = 0; i < 8; i++) a[i] = sy[(r0 + i) * TSTRIDE + k];
        float4 w0 = *reinterpret_cast<const float4*>(&sW[k * 128 + c0]);
        float4 w1 = *reinterpret_cast<const float4*>(&sW[k * 128 + c0 + 4]);
        float w[8] = {w0.x, w0.y, w0.z, w0.w, w1.x, w1.y, w1.z, w1.w};
#pragma unroll
        for (int i = 0; i < 8; i++)
#pragma unroll
            for (int j = 0; j < 8; j++) acc[i][j] = fmaf(a[i], w[j], acc[i][j]);
    }
    __syncthreads();

#pragma unroll
    for (int i = 0; i < 8; i++)
#pragma unroll
        for (int j = 0; j < 8; j++)
            sy[(r0 + i) * TSTRIDE + c0 + j] = sspf(acc[i][j] + sb[c0 + j]);
    __syncthreads();

    for (int i = tid; i < 4096; i += 256)
        reinterpret_cast<float4*>(sW)[i] = reinterpret_cast<const float4*>(Wo2)[i];
    if (tid < 128) sb[tid] = bo2[tid];
    __syncthreads();

    float acc2[8][8];
#pragma unroll
    for (int i = 0; i < 8; i++)
#pragma unroll
        for (int j = 0; j < 8; j++) acc2[i][j] = 0.f;

    for (int k = 0; k < 128; k++) {
        float a[8];
#pragma unroll
        for (int i = 0; i < 8; i++) a[i] = sy[(r0 + i) * TSTRIDE + k];
        float4 w0 = *reinterpret_cast<const float4*>(&sW[k * 128 + c0]);
        float4 w1 = *reinterpret_cast<const float4*>(&sW[k * 128 + c0 + 4]);
        float w[8] = {w0.x, w0.y, w0.z, w0.w, w1.x, w1.y, w1.z, w1.w};
#pragma unroll
        for (int i = 0; i < 8; i++)
#pragma unroll
            for (int j = 0; j < 8; j++) acc2[i][j] = fmaf(a[i], w[j], acc2[i][j]);
    }

#pragma unroll
    for (int i = 0; i < 8; i++) {
        int r = rbase + r0 + i;
        if (r < N_ATOMS) {
            float4 o0 = make_float4(acc2[i][0] + sb[c0 + 0], acc2[i][1] + sb[c0 + 1],
                                    acc2[i][2] + sb[c0 + 2], acc2[i][3] + sb[c0 + 3]);
            float4 o1 = make_float4(acc2[i][4] + sb[c0 + 4], acc2[i][5] + sb[c0 + 5],
                                    acc2[i][6] + sb[c0 + 6], acc2[i][7] + sb[c0 + 7]);
            float4* dst = reinterpret_cast<float4*>(&out[(size_t)r * 128 + c0]);
            dst[0] = o0; dst[1] = o1;
        }
    }
}

// ---------------------------------------------------------------------------
extern "C" void kernel_launch(void* const* d_in, const int* in_sizes, int n_in,
                              void* d_out, int out_size) {
    const float* x      = (const float*)d_in[0];
    const float* f_ij   = (const float*)d_in[1];
    const float* rcut   = (const float*)d_in[2];
    const int*   idx_i  = (const int*)d_in[3];
    const int*   idx_j  = (const int*)d_in[4];
    const float* W_in2f = (const float*)d_in[5];
    const float* W_f1   = (const float*)d_in[6];
    const float* b_f1   = (const float*)d_in[7];
    const float* W_f2   = (const float*)d_in[8];
    const float* b_f2   = (const float*)d_in[9];
    const float* W_o1   = (const float*)d_in[10];
    const float* b_o1   = (const float*)d_in[11];
    const float* W_o2   = (const float*)d_in[12];
    const float* b_o2   = (const float*)d_in[13];
    float* out = (float*)d_out;

    const int smemA = (128 * TSTRIDE + 128 * 128) * 4;
    const int smemC = (128 * TSTRIDE + 128 * 128 + 128) * 4;

    cudaFuncSetAttribute(h_kernel, cudaFuncAttributeMaxDynamicSharedMemorySize, smemA);
    cudaFuncSetAttribute(edge_kernel, cudaFuncAttributeMaxDynamicSharedMemorySize, SMEM_EDGE);
    cudaFuncSetAttribute(out_kernel, cudaFuncAttributeMaxDynamicSharedMemorySize, smemC);

    prep_w2_kernel<<<64, 256>>>(W_f2);
    zero_y_kernel<<<512, 256>>>();
    h_kernel<<<(N_ATOMS + 127) / 128, 256, smemA>>>(x, W_in2f);
    edge_kernel<<<N_EDGES / 128, 256, SMEM_EDGE>>>(f_ij, rcut, idx_i, idx_j,
                                                   W_f1, b_f1, b_f2);
    out_kernel<<<(N_ATOMS + 127) / 128, 256, smemC>>>(W_o1, b_o1, W_o2, b_o2, out);
}

// round 7
// speedup vs baseline: 2.1202x; 1.3091x over previous
#include <cuda_runtime.h>
#include <cuda_bf16.h>
#include <cstdint>

#define N_ATOMS 50000
#define N_EDGES 1600000
#define NF      128
#define NRBF    20
#define TSTRIDE 130

// B bf16 tile row stride in elements (128 data + 8 pad -> 272B rows)
#define KSTR 136
#define BTILE_BYTES (128 * KSTR * 2)   // 34816

// ---------------- device globals (no allocation allowed) -------------------
__device__ float g_h[(size_t)N_ATOMS * NF];
__device__ float g_y[(size_t)N_ATOMS * NF];
// W2^T ([n][k], stride KSTR) hi/lo bf16 byte images
__device__ __align__(16) unsigned char g_Bhi[BTILE_BYTES];
__device__ __align__(16) unsigned char g_Blo[BTILE_BYTES];
// W1^T [n=128][k=20] fp32 (for fragment-mapped GEMM1)
__device__ __align__(16) float g_W1T[128 * 20];

__device__ __forceinline__ float sspf(float v) {
    return fmaxf(v, 0.f) + log1pf(__expf(-fabsf(v))) - 0.6931471805599453f;
}

__device__ __forceinline__ uint32_t smem_u32(const void* p) {
    uint32_t a;
    asm("{ .reg .u64 t; cvta.to.shared.u64 t, %1; cvt.u32.u64 %0, t; }" : "=r"(a) : "l"(p));
    return a;
}

__device__ __forceinline__ void ldsm_x4(uint32_t addr, uint32_t r[4]) {
    asm volatile("ldmatrix.sync.aligned.m8n8.x4.shared.b16 {%0,%1,%2,%3}, [%4];"
                 : "=r"(r[0]), "=r"(r[1]), "=r"(r[2]), "=r"(r[3]) : "r"(addr));
}

__device__ __forceinline__ void mma_bf16(float c[4], const uint32_t a[4],
                                         uint32_t b0, uint32_t b1) {
    asm volatile(
        "mma.sync.aligned.m16n8k16.row.col.f32.bf16.bf16.f32 "
        "{%0,%1,%2,%3}, {%4,%5,%6,%7}, {%8,%9}, {%0,%1,%2,%3};"
        : "+f"(c[0]), "+f"(c[1]), "+f"(c[2]), "+f"(c[3])
        : "r"(a[0]), "r"(a[1]), "r"(a[2]), "r"(a[3]), "r"(b0), "r"(b1));
}

// pack two f32 -> bf16x2 (x -> low 16, y -> high 16)
__device__ __forceinline__ uint32_t pack2bf(float lo, float hi) {
    __nv_bfloat162 v = __float22bfloat162_rn(make_float2(lo, hi));
    return *reinterpret_cast<uint32_t*>(&v);
}

// ---------------------------------------------------------------------------
// prep kernels
// ---------------------------------------------------------------------------
__global__ void prep_w2_kernel(const float* __restrict__ W2) {
    int i = blockIdx.x * blockDim.x + threadIdx.x;
    if (i >= 16384) return;
    int k = i >> 7, n = i & 127;
    float v = W2[k * 128 + n];
    __nv_bfloat16 hi = __float2bfloat16(v);
    __nv_bfloat16 lo = __float2bfloat16(v - __bfloat162float(hi));
    uint32_t off = (uint32_t)n * (KSTR * 2) + (uint32_t)k * 2;
    *(__nv_bfloat16*)(g_Bhi + off) = hi;
    *(__nv_bfloat16*)(g_Blo + off) = lo;
}

__global__ void prep_w1t_kernel(const float* __restrict__ W1) {
    int i = blockIdx.x * blockDim.x + threadIdx.x;
    if (i >= 128 * 20) return;
    int n = i / 20, k = i % 20;
    g_W1T[n * 20 + k] = W1[k * 128 + n];
}

__global__ void zero_y_kernel() {
    const int n4 = N_ATOMS * NF / 4;
    float4 z = make_float4(0.f, 0.f, 0.f, 0.f);
    for (int i = blockIdx.x * blockDim.x + threadIdx.x; i < n4;
         i += gridDim.x * blockDim.x)
        reinterpret_cast<float4*>(g_y)[i] = z;
}

// ---------------------------------------------------------------------------
// h = x @ W_in2f
// ---------------------------------------------------------------------------
__global__ void __launch_bounds__(256, 1)
h_kernel(const float* __restrict__ x, const float* __restrict__ W) {
    extern __shared__ float sm[];
    float* sx = sm;
    float* sW = sm + 128 * TSTRIDE;

    const int tid = threadIdx.x;
    const int tx = tid & 15, ty = tid >> 4;
    const int c0 = tx * 8, r0 = ty * 8;
    const int rbase = blockIdx.x * 128;

    for (int i = tid; i < 128 * 32; i += 256)
        reinterpret_cast<float4*>(sW)[i] = reinterpret_cast<const float4*>(W)[i];
    for (int i = tid; i < 128 * 32; i += 256) {
        int r = i >> 5, c4 = (i & 31) * 4;
        float4 v = make_float4(0.f, 0.f, 0.f, 0.f);
        if (rbase + r < N_ATOMS)
            v = reinterpret_cast<const float4*>(x)[(size_t)(rbase + r) * 32 + (i & 31)];
        float* d = &sx[r * TSTRIDE + c4];
        d[0] = v.x; d[1] = v.y; d[2] = v.z; d[3] = v.w;
    }
    __syncthreads();

    float acc[8][8];
#pragma unroll
    for (int i = 0; i < 8; i++)
#pragma unroll
        for (int j = 0; j < 8; j++) acc[i][j] = 0.f;

    for (int k = 0; k < 128; k++) {
        float a[8];
#pragma unroll
        for (int i = 0; i < 8; i++) a[i] = sx[(r0 + i) * TSTRIDE + k];
        float4 w0 = *reinterpret_cast<const float4*>(&sW[k * 128 + c0]);
        float4 w1 = *reinterpret_cast<const float4*>(&sW[k * 128 + c0 + 4]);
        float w[8] = {w0.x, w0.y, w0.z, w0.w, w1.x, w1.y, w1.z, w1.w};
#pragma unroll
        for (int i = 0; i < 8; i++)
#pragma unroll
            for (int j = 0; j < 8; j++) acc[i][j] = fmaf(a[i], w[j], acc[i][j]);
    }

#pragma unroll
    for (int i = 0; i < 8; i++) {
        int r = rbase + r0 + i;
        if (r < N_ATOMS) {
            float4 o0 = make_float4(acc[i][0], acc[i][1], acc[i][2], acc[i][3]);
            float4 o1 = make_float4(acc[i][4], acc[i][5], acc[i][6], acc[i][7]);
            float4* dst = reinterpret_cast<float4*>(&g_h[(size_t)r * 128 + c0]);
            dst[0] = o0; dst[1] = o1;
        }
    }
}

// ---------------------------------------------------------------------------
// Edge kernel: 2 CTAs/SM.  smem (bytes):
//   0      : B_hi (34816)
//   34816  : B_lo (34816)
//   69632  : union { sf (10240) @69632, sW1T (10240) @79872 }
//            { st 128*36*4 = 18432 @69632 }       (aliased after GEMM1)
//   90112  : sb1(512) sb2(512) src(512) sii(512) sjj(512)
// ---------------------------------------------------------------------------
#define OFF_BHI  0
#define OFF_BLO  34816
#define OFF_SF   69632
#define OFF_W1T  79872
#define OFF_ST   69632
#define OFF_B1   90112
#define OFF_B2   90624
#define OFF_RC   91136
#define OFF_II   91648
#define OFF_JJ   92160
#define SMEM_EDGE 92672
#define STSTR 36

__global__ void __launch_bounds__(256, 2)
edge_kernel(const float* __restrict__ f_ij, const float* __restrict__ rcut,
            const int* __restrict__ idx_i, const int* __restrict__ idx_j,
            const float* __restrict__ b1, const float* __restrict__ b2) {
    extern __shared__ __align__(16) unsigned char smraw[];
    const int tid = threadIdx.x;
    const int wid = tid >> 5, lane = tid & 31;
    const uint32_t sbase = smem_u32(smraw);
    const int ebase = blockIdx.x * 128;

    float* sf   = (float*)(smraw + OFF_SF);
    float* sW1T = (float*)(smraw + OFF_W1T);
    float* sb1  = (float*)(smraw + OFF_B1);
    float* sb2  = (float*)(smraw + OFF_B2);
    float* src  = (float*)(smraw + OFF_RC);
    int*   sii  = (int*)(smraw + OFF_II);
    int*   sjj  = (int*)(smraw + OFF_JJ);
    float* st   = (float*)(smraw + OFF_ST);

    // ---- stage B images, f tile, W1T, misc
    {
        uint4* d1 = (uint4*)(smraw + OFF_BHI);
        uint4* d2 = (uint4*)(smraw + OFF_BLO);
        const uint4* s1 = (const uint4*)g_Bhi;
        const uint4* s2 = (const uint4*)g_Blo;
        for (int i = tid; i < BTILE_BYTES / 16; i += 256) { d1[i] = s1[i]; d2[i] = s2[i]; }
        for (int i = tid; i < 640; i += 256)
            ((float4*)sf)[i] = ((const float4*)(f_ij + (size_t)ebase * NRBF))[i];
        for (int i = tid; i < 640; i += 256)
            ((float4*)sW1T)[i] = ((const float4*)g_W1T)[i];
        if (tid < 128) {
            sb1[tid] = b1[tid];
            sb2[tid] = b2[tid];
            src[tid] = rcut[ebase + tid];
            sii[tid] = idx_i[ebase + tid];
            sjj[tid] = idx_j[ebase + tid];
        }
    }
    __syncthreads();

    // ---- GEMM1 (FFMA), fragment-mapped: thread owns rows r0,r0+8, cols 8n+2q(+1)
    const int q = lane & 3, gr = lane >> 2;
    const int r0 = wid * 16 + gr, r1 = r0 + 8;

    uint32_t a_hi[8][4], a_lo[8][4];
    {
        float4 fa[5], fb[5];
#pragma unroll
        for (int j = 0; j < 5; j++) {
            fa[j] = *(const float4*)(sf + r0 * 20 + 4 * j);
            fb[j] = *(const float4*)(sf + r1 * 20 + 4 * j);
        }
#pragma unroll
        for (int n = 0; n < 16; n++) {
            const int c0 = 8 * n + 2 * q;
            const float* w0 = sW1T + c0 * 20;
            const float* w1 = w0 + 20;
            float t00 = 0.f, t01 = 0.f, t10 = 0.f, t11 = 0.f;
#pragma unroll
            for (int j = 0; j < 5; j++) {
                float4 w0v = *(const float4*)(w0 + 4 * j);
                float4 w1v = *(const float4*)(w1 + 4 * j);
                t00 = fmaf(fa[j].x, w0v.x, t00); t00 = fmaf(fa[j].y, w0v.y, t00);
                t00 = fmaf(fa[j].z, w0v.z, t00); t00 = fmaf(fa[j].w, w0v.w, t00);
                t01 = fmaf(fa[j].x, w1v.x, t01); t01 = fmaf(fa[j].y, w1v.y, t01);
                t01 = fmaf(fa[j].z, w1v.z, t01); t01 = fmaf(fa[j].w, w1v.w, t01);
                t10 = fmaf(fb[j].x, w0v.x, t10); t10 = fmaf(fb[j].y, w0v.y, t10);
                t10 = fmaf(fb[j].z, w0v.z, t10); t10 = fmaf(fb[j].w, w0v.w, t10);
                t11 = fmaf(fb[j].x, w1v.x, t11); t11 = fmaf(fb[j].y, w1v.y, t11);
                t11 = fmaf(fb[j].z, w1v.z, t11); t11 = fmaf(fb[j].w, w1v.w, t11);
            }
            float2 bv = *(const float2*)(sb1 + c0);
            t00 = sspf(t00 + bv.x); t01 = sspf(t01 + bv.y);
            t10 = sspf(t10 + bv.x); t11 = sspf(t11 + bv.y);
            uint32_t h0 = pack2bf(t00, t01);
            uint32_t h1 = pack2bf(t10, t11);
            float e00 = t00 - __uint_as_float(h0 << 16);
            float e01 = t01 - __uint_as_float(h0 & 0xFFFF0000u);
            float e10 = t10 - __uint_as_float(h1 << 16);
            float e11 = t11 - __uint_as_float(h1 & 0xFFFF0000u);
            uint32_t l0 = pack2bf(e00, e01);
            uint32_t l1 = pack2bf(e10, e11);
            const int kk = n >> 1, hf = (n & 1) * 2;
            a_hi[kk][hf] = h0; a_hi[kk][hf + 1] = h1;
            a_lo[kk][hf] = l0; a_lo[kk][hf + 1] = l1;
        }
    }
    __syncthreads();   // sf/sW1T reads complete; st may now alias them

    // per-thread epilogue constants
    const float rc0 = src[r0], rc1 = src[r1];
    const int   j0 = sjj[r0],  j1 = sjj[r1];
    const float2* const h0p = (const float2*)(g_h + (size_t)j0 * 128);
    const float2* const h1p = (const float2*)(g_h + (size_t)j1 * 128);

    const int koff = (lane >> 4) << 3;
    const int nlo = lane & 15;
    const int stx = tid & 15;      // scatter: 2 cols
    const int sty = tid >> 4;      // scatter: 8 edges

    // ---- 4 column-quarter passes
#pragma unroll
    for (int p = 0; p < 4; p++) {
        const int colbase = p * 32;

        float acc[4][4];
#pragma unroll
        for (int t = 0; t < 4; t++)
#pragma unroll
            for (int j = 0; j < 4; j++) acc[t][j] = 0.f;

#pragma unroll
        for (int kk = 0; kk < 8; kk++) {
            const uint32_t kb = (uint32_t)(kk * 16 + koff) * 2;
#pragma unroll
            for (int np = 0; np < 2; np++) {
                const int nrow = colbase + np * 16 + nlo;
                const uint32_t baddr = (uint32_t)nrow * (KSTR * 2) + kb;
                uint32_t bh[4], bl[4];
                ldsm_x4(sbase + OFF_BHI + baddr, bh);
                ldsm_x4(sbase + OFF_BLO + baddr, bl);
                mma_bf16(acc[2 * np],     a_hi[kk], bh[0], bh[2]);
                mma_bf16(acc[2 * np],     a_hi[kk], bl[0], bl[2]);
                mma_bf16(acc[2 * np],     a_lo[kk], bh[0], bh[2]);
                mma_bf16(acc[2 * np + 1], a_hi[kk], bh[1], bh[3]);
                mma_bf16(acc[2 * np + 1], a_hi[kk], bl[1], bl[3]);
                mma_bf16(acc[2 * np + 1], a_lo[kk], bh[1], bh[3]);
            }
        }

        // epilogue: modulate + stage to st [128][STSTR]
#pragma unroll
        for (int nt = 0; nt < 4; nt++) {
            const int c = colbase + 8 * nt + 2 * q;   // absolute col (even)
            float2 bv = *(const float2*)(sb2 + c);
            float2 hv0 = h0p[c >> 1];
            float2 hv1 = h1p[c >> 1];
            float2 v0, v1;
            v0.x = (acc[nt][0] + bv.x) * rc0 * hv0.x;
            v0.y = (acc[nt][1] + bv.y) * rc0 * hv0.y;
            v1.x = (acc[nt][2] + bv.x) * rc1 * hv1.x;
            v1.y = (acc[nt][3] + bv.y) * rc1 * hv1.y;
            *(float2*)(st + r0 * STSTR + (c - colbase)) = v0;
            *(float2*)(st + r1 * STSTR + (c - colbase)) = v1;
        }
        __syncthreads();

        // scatter: run-accumulate (idx_i sorted), 2 cols per thread
        {
            float2 run = make_float2(0.f, 0.f);
            int cur = -1;
#pragma unroll
            for (int i = 0; i < 8; i++) {
                const int e = sty * 8 + i;
                const int ii = sii[e];
                if (ii != cur) {
                    if (cur >= 0) {
                        float* y0 = g_y + (size_t)cur * 128 + colbase + 2 * stx;
                        atomicAdd(y0, run.x);
                        atomicAdd(y0 + 1, run.y);
                    }
                    cur = ii;
                    run.x = 0.f; run.y = 0.f;
                }
                float2 v = *(const float2*)(st + e * STSTR + 2 * stx);
                run.x += v.x; run.y += v.y;
            }
            float* y0 = g_y + (size_t)cur * 128 + colbase + 2 * stx;
            atomicAdd(y0, run.x);
            atomicAdd(y0 + 1, run.y);
        }
        __syncthreads();
    }
}

// ---------------------------------------------------------------------------
// out = ssp(y @ W_o1 + b_o1) @ W_o2 + b_o2
// ---------------------------------------------------------------------------
__global__ void __launch_bounds__(256, 1)
out_kernel(const float* __restrict__ Wo1, const float* __restrict__ bo1,
           const float* __restrict__ Wo2, const float* __restrict__ bo2,
           float* __restrict__ out) {
    extern __shared__ float sm[];
    float* sy = sm;
    float* sW = sm + 128 * TSTRIDE;
    float* sb = sW + 16384;

    const int tid = threadIdx.x;
    const int tx = tid & 15, ty = tid >> 4;
    const int c0 = tx * 8, r0 = ty * 8;
    const int rbase = blockIdx.x * 128;

    for (int i = tid; i < 4096; i += 256)
        reinterpret_cast<float4*>(sW)[i] = reinterpret_cast<const float4*>(Wo1)[i];
    if (tid < 128) sb[tid] = bo1[tid];
    for (int i = tid; i < 128 * 32; i += 256) {
        int r = i >> 5, c4 = (i & 31) * 4;
        float4 v = make_float4(0.f, 0.f, 0.f, 0.f);
        if (rbase + r < N_ATOMS)
            v = reinterpret_cast<const float4*>(g_y)[(size_t)(rbase + r) * 32 + (i & 31)];
        float* d = &sy[r * TSTRIDE + c4];
        d[0] = v.x; d[1] = v.y; d[2] = v.z; d[3] = v.w;
    }
    __syncthreads();

    float acc[8][8];
#pragma unroll
    for (int i = 0; i < 8; i++)
#pragma unroll
        for (int j = 0; j < 8; j++) acc[i][j] = 0.f;

    for (int k = 0; k < 128; k++) {
        float a[8];
#pragma unroll
        for (int i = 0; i < 8; i++) a[i] = sy[(r0 + i) * TSTRIDE + k];
        float4 w0 = *reinterpret_cast<const float4*>(&sW[k * 128 + c0]);
        float4 w1 = *reinterpret_cast<const float4*>(&sW[k * 128 + c0 + 4]);
        float w[8] = {w0.x, w0.y, w0.z, w0.w, w1.x, w1.y, w1.z, w1.w};
#pragma unroll
        for (int i = 0; i < 8; i++)
#pragma unroll
            for (int j = 0; j < 8; j++) acc[i][j] = fmaf(a[i], w[j], acc[i][j]);
    }
    __syncthreads();

#pragma unroll
    for (int i = 0; i < 8; i++)
#pragma unroll
        for (int j = 0; j < 8; j++)
            sy[(r0 + i) * TSTRIDE + c0 + j] = sspf(acc[i][j] + sb[c0 + j]);
    __syncthreads();

    for (int i = tid; i < 4096; i += 256)
        reinterpret_cast<float4*>(sW)[i] = reinterpret_cast<const float4*>(Wo2)[i];
    if (tid < 128) sb[tid] = bo2[tid];
    __syncthreads();

    float acc2[8][8];
#pragma unroll
    for (int i = 0; i < 8; i++)
#pragma unroll
        for (int j = 0; j < 8; j++) acc2[i][j] = 0.f;

    for (int k = 0; k < 128; k++) {
        float a[8];
#pragma unroll
        for (int i = 0; i < 8; i++) a[i] = sy[(r0 + i) * TSTRIDE + k];
        float4 w0 = *reinterpret_cast<const float4*>(&sW[k * 128 + c0]);
        float4 w1 = *reinterpret_cast<const float4*>(&sW[k * 128 + c0 + 4]);
        float w[8] = {w0.x, w0.y, w0.z, w0.w, w1.x, w1.y, w1.z, w1.w};
#pragma unroll
        for (int i = 0; i < 8; i++)
#pragma unroll
            for (int j = 0; j < 8; j++) acc2[i][j] = fmaf(a[i], w[j], acc2[i][j]);
    }

#pragma unroll
    for (int i = 0; i < 8; i++) {
        int r = rbase + r0 + i;
        if (r < N_ATOMS) {
            float4 o0 = make_float4(acc2[i][0] + sb[c0 + 0], acc2[i][1] + sb[c0 + 1],
                                    acc2[i][2] + sb[c0 + 2], acc2[i][3] + sb[c0 + 3]);
            float4 o1 = make_float4(acc2[i][4] + sb[c0 + 4], acc2[i][5] + sb[c0 + 5],
                                    acc2[i][6] + sb[c0 + 6], acc2[i][7] + sb[c0 + 7]);
            float4* dst = reinterpret_cast<float4*>(&out[(size_t)r * 128 + c0]);
            dst[0] = o0; dst[1] = o1;
        }
    }
}

// ---------------------------------------------------------------------------
extern "C" void kernel_launch(void* const* d_in, const int* in_sizes, int n_in,
                              void* d_out, int out_size) {
    const float* x      = (const float*)d_in[0];
    const float* f_ij   = (const float*)d_in[1];
    const float* rcut   = (const float*)d_in[2];
    const int*   idx_i  = (const int*)d_in[3];
    const int*   idx_j  = (const int*)d_in[4];
    const float* W_in2f = (const float*)d_in[5];
    const float* W_f1   = (const float*)d_in[6];
    const float* b_f1   = (const float*)d_in[7];
    const float* W_f2   = (const float*)d_in[8];
    const float* b_f2   = (const float*)d_in[9];
    const float* W_o1   = (const float*)d_in[10];
    const float* b_o1   = (const float*)d_in[11];
    const float* W_o2   = (const float*)d_in[12];
    const float* b_o2   = (const float*)d_in[13];
    float* out = (float*)d_out;

    const int smemA = (128 * TSTRIDE + 128 * 128) * 4;
    const int smemC = (128 * TSTRIDE + 128 * 128 + 128) * 4;

    cudaFuncSetAttribute(h_kernel, cudaFuncAttributeMaxDynamicSharedMemorySize, smemA);
    cudaFuncSetAttribute(edge_kernel, cudaFuncAttributeMaxDynamicSharedMemorySize, SMEM_EDGE);
    cudaFuncSetAttribute(out_kernel, cudaFuncAttributeMaxDynamicSharedMemorySize, smemC);

    prep_w2_kernel<<<64, 256>>>(W_f2);
    prep_w1t_kernel<<<10, 256>>>(W_f1);
    zero_y_kernel<<<512, 256>>>();
    h_kernel<<<(N_ATOMS + 127) / 128, 256, smemA>>>(x, W_in2f);
    edge_kernel<<<N_EDGES / 128, 256, SMEM_EDGE>>>(f_ij, rcut, idx_i, idx_j,
                                                   b_f1, b_f2);
    out_kernel<<<(N_ATOMS + 127) / 128, 256, smemC>>>(W_o1, b_o1, W_o2, b_o2, out);
}

// round 8
// speedup vs baseline: 2.5375x; 1.1968x over previous
#include <cuda_runtime.h>
#include <cuda_bf16.h>
#include <cstdint>

#define N_ATOMS 50000
#define N_EDGES 1600000
#define NF      128
#define NRBF    20
#define TSTRIDE 130

// B (W2^T) bf16 tile row stride in elements (128 data + 8 pad -> 272B rows)
#define KSTR 136
#define BTILE_BYTES (128 * KSTR * 2)   // 34816
// W1^T / f tile row stride: 40 bf16 = 80B (banks stride 20 -> conflict-free ldsm)
#define W1STR 40
#define W1TILE_BYTES (128 * W1STR * 2) // 10240

// ---------------- device globals (no allocation allowed) -------------------
__device__ float g_h[(size_t)N_ATOMS * NF];
__device__ float g_y[(size_t)N_ATOMS * NF];
// W2^T ([n][k], stride KSTR) hi/lo bf16 byte images
__device__ __align__(16) unsigned char g_Bhi[BTILE_BYTES];
__device__ __align__(16) unsigned char g_Blo[BTILE_BYTES];
// W1^T ([n=128][k=40], k>=20 zero) hi/lo bf16 byte images
__device__ __align__(16) unsigned char g_W1h[W1TILE_BYTES];
__device__ __align__(16) unsigned char g_W1l[W1TILE_BYTES];

__device__ __forceinline__ float sspf(float v) {
    return fmaxf(v, 0.f) + log1pf(__expf(-fabsf(v))) - 0.6931471805599453f;
}

__device__ __forceinline__ uint32_t smem_u32(const void* p) {
    uint32_t a;
    asm("{ .reg .u64 t; cvta.to.shared.u64 t, %1; cvt.u32.u64 %0, t; }" : "=r"(a) : "l"(p));
    return a;
}

__device__ __forceinline__ void ldsm_x4(uint32_t addr, uint32_t r[4]) {
    asm volatile("ldmatrix.sync.aligned.m8n8.x4.shared.b16 {%0,%1,%2,%3}, [%4];"
                 : "=r"(r[0]), "=r"(r[1]), "=r"(r[2]), "=r"(r[3]) : "r"(addr));
}

__device__ __forceinline__ void mma_bf16(float c[4], const uint32_t a[4],
                                         uint32_t b0, uint32_t b1) {
    asm volatile(
        "mma.sync.aligned.m16n8k16.row.col.f32.bf16.bf16.f32 "
        "{%0,%1,%2,%3}, {%4,%5,%6,%7}, {%8,%9}, {%0,%1,%2,%3};"
        : "+f"(c[0]), "+f"(c[1]), "+f"(c[2]), "+f"(c[3])
        : "r"(a[0]), "r"(a[1]), "r"(a[2]), "r"(a[3]), "r"(b0), "r"(b1));
}

// pack two f32 -> bf16x2 (x -> low 16, y -> high 16)
__device__ __forceinline__ uint32_t pack2bf(float lo, float hi) {
    __nv_bfloat162 v = __float22bfloat162_rn(make_float2(lo, hi));
    return *reinterpret_cast<uint32_t*>(&v);
}

// ---------------------------------------------------------------------------
// prep kernels
// ---------------------------------------------------------------------------
__global__ void prep_w2_kernel(const float* __restrict__ W2) {
    int i = blockIdx.x * blockDim.x + threadIdx.x;
    if (i >= 16384) return;
    int k = i >> 7, n = i & 127;
    float v = W2[k * 128 + n];
    __nv_bfloat16 hi = __float2bfloat16(v);
    __nv_bfloat16 lo = __float2bfloat16(v - __bfloat162float(hi));
    uint32_t off = (uint32_t)n * (KSTR * 2) + (uint32_t)k * 2;
    *(__nv_bfloat16*)(g_Bhi + off) = hi;
    *(__nv_bfloat16*)(g_Blo + off) = lo;
}

__global__ void prep_w1_kernel(const float* __restrict__ W1) {
    int i = blockIdx.x * blockDim.x + threadIdx.x;
    if (i >= 128 * W1STR) return;
    int n = i / W1STR, k = i % W1STR;
    float v = (k < NRBF) ? W1[k * 128 + n] : 0.f;
    __nv_bfloat16 hi = __float2bfloat16(v);
    __nv_bfloat16 lo = __float2bfloat16(v - __bfloat162float(hi));
    uint32_t off = (uint32_t)n * (W1STR * 2) + (uint32_t)k * 2;
    *(__nv_bfloat16*)(g_W1h + off) = hi;
    *(__nv_bfloat16*)(g_W1l + off) = lo;
}

__global__ void zero_y_kernel() {
    const int n4 = N_ATOMS * NF / 4;
    float4 z = make_float4(0.f, 0.f, 0.f, 0.f);
    for (int i = blockIdx.x * blockDim.x + threadIdx.x; i < n4;
         i += gridDim.x * blockDim.x)
        reinterpret_cast<float4*>(g_y)[i] = z;
}

// ---------------------------------------------------------------------------
// h = x @ W_in2f      (512 threads, 4x8 micro-tile)
// ---------------------------------------------------------------------------
__global__ void __launch_bounds__(512, 1)
h_kernel(const float* __restrict__ x, const float* __restrict__ W) {
    extern __shared__ float sm[];
    float* sx = sm;
    float* sW = sm + 128 * TSTRIDE;

    const int tid = threadIdx.x;
    const int tx = tid & 15, ty = tid >> 4;
    const int c0 = tx * 8, r0 = ty * 4;
    const int rbase = blockIdx.x * 128;

    for (int i = tid; i < 128 * 32; i += 512)
        reinterpret_cast<float4*>(sW)[i] = reinterpret_cast<const float4*>(W)[i];
    for (int i = tid; i < 128 * 32; i += 512) {
        int r = i >> 5, c4 = (i & 31) * 4;
        float4 v = make_float4(0.f, 0.f, 0.f, 0.f);
        if (rbase + r < N_ATOMS)
            v = reinterpret_cast<const float4*>(x)[(size_t)(rbase + r) * 32 + (i & 31)];
        float* d = &sx[r * TSTRIDE + c4];
        d[0] = v.x; d[1] = v.y; d[2] = v.z; d[3] = v.w;
    }
    __syncthreads();

    float acc[4][8];
#pragma unroll
    for (int i = 0; i < 4; i++)
#pragma unroll
        for (int j = 0; j < 8; j++) acc[i][j] = 0.f;

    for (int k = 0; k < 128; k++) {
        float a[4];
#pragma unroll
        for (int i = 0; i < 4; i++) a[i] = sx[(r0 + i) * TSTRIDE + k];
        float4 w0 = *reinterpret_cast<const float4*>(&sW[k * 128 + c0]);
        float4 w1 = *reinterpret_cast<const float4*>(&sW[k * 128 + c0 + 4]);
        float w[8] = {w0.x, w0.y, w0.z, w0.w, w1.x, w1.y, w1.z, w1.w};
#pragma unroll
        for (int i = 0; i < 4; i++)
#pragma unroll
            for (int j = 0; j < 8; j++) acc[i][j] = fmaf(a[i], w[j], acc[i][j]);
    }

#pragma unroll
    for (int i = 0; i < 4; i++) {
        int r = rbase + r0 + i;
        if (r < N_ATOMS) {
            float4 o0 = make_float4(acc[i][0], acc[i][1], acc[i][2], acc[i][3]);
            float4 o1 = make_float4(acc[i][4], acc[i][5], acc[i][6], acc[i][7]);
            float4* dst = reinterpret_cast<float4*>(&g_h[(size_t)r * 128 + c0]);
            dst[0] = o0; dst[1] = o1;
        }
    }
}

// ---------------------------------------------------------------------------
// Edge kernel: 2 CTAs/SM, both GEMMs on tensor cores.  smem (bytes):
//   0      : B_hi (34816)
//   34816  : B_lo (34816)
//   69632  : f_hi  (10240)  \  st (18432B) aliases f_hi..f_lo after GEMM1
//   79872  : f_lo  (10240)  /
//   90112  : W1_hi (10240)
//   100352 : W1_lo (10240)
//   110592 : sb1(512) sb2(512) src(512) sii(512) sjj(512)  -> end 113152
// ---------------------------------------------------------------------------
#define OFF_BHI  0
#define OFF_BLO  34816
#define OFF_FH   69632
#define OFF_FL   79872
#define OFF_W1H  90112
#define OFF_W1L  100352
#define OFF_ST   69632
#define OFF_B1   110592
#define OFF_B2   111104
#define OFF_RC   111616
#define OFF_II   112128
#define OFF_JJ   112640
#define SMEM_EDGE 113152
#define STSTR 36

__global__ void __launch_bounds__(256, 2)
edge_kernel(const float* __restrict__ f_ij, const float* __restrict__ rcut,
            const int* __restrict__ idx_i, const int* __restrict__ idx_j,
            const float* __restrict__ b1, const float* __restrict__ b2) {
    extern __shared__ __align__(16) unsigned char smraw[];
    const int tid = threadIdx.x;
    const int wid = tid >> 5, lane = tid & 31;
    const uint32_t sbase = smem_u32(smraw);
    const int ebase = blockIdx.x * 128;

    float* sb1  = (float*)(smraw + OFF_B1);
    float* sb2  = (float*)(smraw + OFF_B2);
    float* src  = (float*)(smraw + OFF_RC);
    int*   sii  = (int*)(smraw + OFF_II);
    int*   sjj  = (int*)(smraw + OFF_JJ);
    float* st   = (float*)(smraw + OFF_ST);

    // f LDG into registers (written to smem after the zeroing sync)
    const int fe = tid >> 1, fk0 = (tid & 1) * 10;
    float2 fv[5];
    {
        const float2* fg = (const float2*)(f_ij + (size_t)ebase * NRBF);
        const int fb = fe * 10 + (fk0 >> 1);
#pragma unroll
        for (int j = 0; j < 5; j++) fv[j] = fg[fb + j];
    }

    // ---- stage: B images, W1 images, zero f buffers, misc
    {
        uint4* d1 = (uint4*)(smraw + OFF_BHI);
        uint4* d2 = (uint4*)(smraw + OFF_BLO);
        const uint4* s1 = (const uint4*)g_Bhi;
        const uint4* s2 = (const uint4*)g_Blo;
        for (int i = tid; i < BTILE_BYTES / 16; i += 256) { d1[i] = s1[i]; d2[i] = s2[i]; }
        uint4* w1 = (uint4*)(smraw + OFF_W1H);
        uint4* w2 = (uint4*)(smraw + OFF_W1L);
        const uint4* t1 = (const uint4*)g_W1h;
        const uint4* t2 = (const uint4*)g_W1l;
        for (int i = tid; i < W1TILE_BYTES / 16; i += 256) { w1[i] = t1[i]; w2[i] = t2[i]; }
        uint4 z = make_uint4(0, 0, 0, 0);
        uint4* fh = (uint4*)(smraw + OFF_FH);
        uint4* fl = (uint4*)(smraw + OFF_FL);
        for (int i = tid; i < W1TILE_BYTES / 16; i += 256) { fh[i] = z; fl[i] = z; }
        if (tid < 128) {
            sb1[tid] = b1[tid];
            sb2[tid] = b2[tid];
            src[tid] = rcut[ebase + tid];
            sii[tid] = idx_i[ebase + tid];
            sjj[tid] = idx_j[ebase + tid];
        }
    }
    __syncthreads();

    // ---- convert f -> bf16 hi/lo into smem (cols fk0..fk0+9 of row fe)
    {
        uint32_t* fh = (uint32_t*)(smraw + OFF_FH);
        uint32_t* fl = (uint32_t*)(smraw + OFF_FL);
        const int base = (fe * (W1STR * 2) + fk0 * 2) >> 2;  // u32 index
#pragma unroll
        for (int j = 0; j < 5; j++) {
            float v0 = fv[j].x, v1 = fv[j].y;
            uint32_t h = pack2bf(v0, v1);
            float e0 = v0 - __uint_as_float(h << 16);
            float e1 = v1 - __uint_as_float(h & 0xFFFF0000u);
            fh[base + j] = h;
            fl[base + j] = pack2bf(e0, e1);
        }
    }
    __syncthreads();

    const int q = lane & 3, gr = lane >> 2;
    const int r0 = wid * 16 + gr, r1 = r0 + 8;
    const int koff = (lane >> 4) << 3;
    const int nlo = lane & 15;

    // ---- GEMM1 on tensor cores: t = ssp(f @ W1 + b1)
    uint32_t a_hi[8][4], a_lo[8][4];
    {
        float acc1[16][4];
#pragma unroll
        for (int t = 0; t < 16; t++)
#pragma unroll
            for (int j = 0; j < 4; j++) acc1[t][j] = 0.f;

        const uint32_t afh = sbase + OFF_FH + (uint32_t)(wid * 16 + nlo) * (W1STR * 2);
        const uint32_t afl = sbase + OFF_FL + (uint32_t)(wid * 16 + nlo) * (W1STR * 2);
#pragma unroll
        for (int kk = 0; kk < 2; kk++) {
            const uint32_t kb = (uint32_t)(kk * 16 + koff) * 2;
            uint32_t fh4[4], fl4[4];
            ldsm_x4(afh + kb, fh4);
            ldsm_x4(afl + kb, fl4);
#pragma unroll
            for (int ntp = 0; ntp < 8; ntp++) {
                const uint32_t baddr = (uint32_t)(ntp * 16 + nlo) * (W1STR * 2) + kb;
                uint32_t wh[4], wl[4];
                ldsm_x4(sbase + OFF_W1H + baddr, wh);
                ldsm_x4(sbase + OFF_W1L + baddr, wl);
                mma_bf16(acc1[2 * ntp],     fh4, wh[0], wh[2]);
                mma_bf16(acc1[2 * ntp],     fh4, wl[0], wl[2]);
                mma_bf16(acc1[2 * ntp],     fl4, wh[0], wh[2]);
                mma_bf16(acc1[2 * ntp + 1], fh4, wh[1], wh[3]);
                mma_bf16(acc1[2 * ntp + 1], fh4, wl[1], wl[3]);
                mma_bf16(acc1[2 * ntp + 1], fl4, wh[1], wh[3]);
            }
        }

        // bias + ssp + hi/lo split -> GEMM2 A fragments
#pragma unroll
        for (int n = 0; n < 16; n++) {
            const int c0 = 8 * n + 2 * q;
            float2 bv = *(const float2*)(sb1 + c0);
            float t00 = sspf(acc1[n][0] + bv.x);
            float t01 = sspf(acc1[n][1] + bv.y);
            float t10 = sspf(acc1[n][2] + bv.x);
            float t11 = sspf(acc1[n][3] + bv.y);
            uint32_t h0 = pack2bf(t00, t01);
            uint32_t h1 = pack2bf(t10, t11);
            float e00 = t00 - __uint_as_float(h0 << 16);
            float e01 = t01 - __uint_as_float(h0 & 0xFFFF0000u);
            float e10 = t10 - __uint_as_float(h1 << 16);
            float e11 = t11 - __uint_as_float(h1 & 0xFFFF0000u);
            const int kk = n >> 1, hf = (n & 1) * 2;
            a_hi[kk][hf] = h0; a_hi[kk][hf + 1] = h1;
            a_lo[kk][hf] = pack2bf(e00, e01);
            a_lo[kk][hf + 1] = pack2bf(e10, e11);
        }
    }
    __syncthreads();   // f/W1 reads complete; st may now alias f region

    // per-thread epilogue constants
    const float rc0 = src[r0], rc1 = src[r1];
    const int   j0 = sjj[r0],  j1 = sjj[r1];
    const float2* const h0p = (const float2*)(g_h + (size_t)j0 * 128);
    const float2* const h1p = (const float2*)(g_h + (size_t)j1 * 128);

    const int stx = tid & 15;      // scatter: 2 cols
    const int sty = tid >> 4;      // scatter: 8 edges

    // ---- 4 column-quarter passes of GEMM2 + scatter
#pragma unroll
    for (int p = 0; p < 4; p++) {
        const int colbase = p * 32;

        float acc[4][4];
#pragma unroll
        for (int t = 0; t < 4; t++)
#pragma unroll
            for (int j = 0; j < 4; j++) acc[t][j] = 0.f;

#pragma unroll
        for (int kk = 0; kk < 8; kk++) {
            const uint32_t kb = (uint32_t)(kk * 16 + koff) * 2;
#pragma unroll
            for (int np = 0; np < 2; np++) {
                const int nrow = colbase + np * 16 + nlo;
                const uint32_t baddr = (uint32_t)nrow * (KSTR * 2) + kb;
                uint32_t bh[4], bl[4];
                ldsm_x4(sbase + OFF_BHI + baddr, bh);
                ldsm_x4(sbase + OFF_BLO + baddr, bl);
                mma_bf16(acc[2 * np],     a_hi[kk], bh[0], bh[2]);
                mma_bf16(acc[2 * np],     a_hi[kk], bl[0], bl[2]);
                mma_bf16(acc[2 * np],     a_lo[kk], bh[0], bh[2]);
                mma_bf16(acc[2 * np + 1], a_hi[kk], bh[1], bh[3]);
                mma_bf16(acc[2 * np + 1], a_hi[kk], bl[1], bl[3]);
                mma_bf16(acc[2 * np + 1], a_lo[kk], bh[1], bh[3]);
            }
        }

        // epilogue: modulate + stage to st [128][STSTR]
#pragma unroll
        for (int nt = 0; nt < 4; nt++) {
            const int c = colbase + 8 * nt + 2 * q;   // absolute col (even)
            float2 bv = *(const float2*)(sb2 + c);
            float2 hv0 = h0p[c >> 1];
            float2 hv1 = h1p[c >> 1];
            float2 v0, v1;
            v0.x = (acc[nt][0] + bv.x) * rc0 * hv0.x;
            v0.y = (acc[nt][1] + bv.y) * rc0 * hv0.y;
            v1.x = (acc[nt][2] + bv.x) * rc1 * hv1.x;
            v1.y = (acc[nt][3] + bv.y) * rc1 * hv1.y;
            *(float2*)(st + r0 * STSTR + (c - colbase)) = v0;
            *(float2*)(st + r1 * STSTR + (c - colbase)) = v1;
        }
        __syncthreads();

        // scatter: run-accumulate (idx_i sorted), 2 cols per thread
        {
            float2 run = make_float2(0.f, 0.f);
            int cur = -1;
#pragma unroll
            for (int i = 0; i < 8; i++) {
                const int e = sty * 8 + i;
                const int ii = sii[e];
                if (ii != cur) {
                    if (cur >= 0) {
                        float* y0 = g_y + (size_t)cur * 128 + colbase + 2 * stx;
                        atomicAdd(y0, run.x);
                        atomicAdd(y0 + 1, run.y);
                    }
                    cur = ii;
                    run.x = 0.f; run.y = 0.f;
                }
                float2 v = *(const float2*)(st + e * STSTR + 2 * stx);
                run.x += v.x; run.y += v.y;
            }
            float* y0 = g_y + (size_t)cur * 128 + colbase + 2 * stx;
            atomicAdd(y0, run.x);
            atomicAdd(y0 + 1, run.y);
        }
        __syncthreads();
    }
}

// ---------------------------------------------------------------------------
// out = ssp(y @ W_o1 + b_o1) @ W_o2 + b_o2   (512 threads, 4x8 micro-tile)
// ---------------------------------------------------------------------------
__global__ void __launch_bounds__(512, 1)
out_kernel(const float* __restrict__ Wo1, const float* __restrict__ bo1,
           const float* __restrict__ Wo2, const float* __restrict__ bo2,
           float* __restrict__ out) {
    extern __shared__ float sm[];
    float* sy = sm;
    float* sW = sm + 128 * TSTRIDE;
    float* sb = sW + 16384;

    const int tid = threadIdx.x;
    const int tx = tid & 15, ty = tid >> 4;
    const int c0 = tx * 8, r0 = ty * 4;
    const int rbase = blockIdx.x * 128;

    for (int i = tid; i < 4096; i += 512)
        reinterpret_cast<float4*>(sW)[i] = reinterpret_cast<const float4*>(Wo1)[i];
    if (tid < 128) sb[tid] = bo1[tid];
    for (int i = tid; i < 128 * 32; i += 512) {
        int r = i >> 5, c4 = (i & 31) * 4;
        float4 v = make_float4(0.f, 0.f, 0.f, 0.f);
        if (rbase + r < N_ATOMS)
            v = reinterpret_cast<const float4*>(g_y)[(size_t)(rbase + r) * 32 + (i & 31)];
        float* d = &sy[r * TSTRIDE + c4];
        d[0] = v.x; d[1] = v.y; d[2] = v.z; d[3] = v.w;
    }
    __syncthreads();

    float acc[4][8];
#pragma unroll
    for (int i = 0; i < 4; i++)
#pragma unroll
        for (int j = 0; j < 8; j++) acc[i][j] = 0.f;

    for (int k = 0; k < 128; k++) {
        float a[4];
#pragma unroll
        for (int i = 0; i < 4; i++) a[i] = sy[(r0 + i) * TSTRIDE + k];
        float4 w0 = *reinterpret_cast<const float4*>(&sW[k * 128 + c0]);
        float4 w1 = *reinterpret_cast<const float4*>(&sW[k * 128 + c0 + 4]);
        float w[8] = {w0.x, w0.y, w0.z, w0.w, w1.x, w1.y, w1.z, w1.w};
#pragma unroll
        for (int i = 0; i < 4; i++)
#pragma unroll
            for (int j = 0; j < 8; j++) acc[i][j] = fmaf(a[i], w[j], acc[i][j]);
    }
    __syncthreads();

#pragma unroll
    for (int i = 0; i < 4; i++)
#pragma unroll
        for (int j = 0; j < 8; j++)
            sy[(r0 + i) * TSTRIDE + c0 + j] = sspf(acc[i][j] + sb[c0 + j]);
    __syncthreads();

    for (int i = tid; i < 4096; i += 512)
        reinterpret_cast<float4*>(sW)[i] = reinterpret_cast<const float4*>(Wo2)[i];
    if (tid < 128) sb[tid] = bo2[tid];
    __syncthreads();

    float acc2[4][8];
#pragma unroll
    for (int i = 0; i < 4; i++)
#pragma unroll
        for (int j = 0; j < 8; j++) acc2[i][j] = 0.f;

    for (int k = 0; k < 128; k++) {
        float a[4];
#pragma unroll
        for (int i = 0; i < 4; i++) a[i] = sy[(r0 + i) * TSTRIDE + k];
        float4 w0 = *reinterpret_cast<const float4*>(&sW[k * 128 + c0]);
        float4 w1 = *reinterpret_cast<const float4*>(&sW[k * 128 + c0 + 4]);
        float w[8] = {w0.x, w0.y, w0.z, w0.w, w1.x, w1.y, w1.z, w1.w};
#pragma unroll
        for (int i = 0; i < 4; i++)
#pragma unroll
            for (int j = 0; j < 8; j++) acc2[i][j] = fmaf(a[i], w[j], acc2[i][j]);
    }

#pragma unroll
    for (int i = 0; i < 4; i++) {
        int r = rbase + r0 + i;
        if (r < N_ATOMS) {
            float4 o0 = make_float4(acc2[i][0] + sb[c0 + 0], acc2[i][1] + sb[c0 + 1],
                                    acc2[i][2] + sb[c0 + 2], acc2[i][3] + sb[c0 + 3]);
            float4 o1 = make_float4(acc2[i][4] + sb[c0 + 4], acc2[i][5] + sb[c0 + 5],
                                    acc2[i][6] + sb[c0 + 6], acc2[i][7] + sb[c0 + 7]);
            float4* dst = reinterpret_cast<float4*>(&out[(size_t)r * 128 + c0]);
            dst[0] = o0; dst[1] = o1;
        }
    }
}

// ---------------------------------------------------------------------------
extern "C" void kernel_launch(void* const* d_in, const int* in_sizes, int n_in,
                              void* d_out, int out_size) {
    const float* x      = (const float*)d_in[0];
    const float* f_ij   = (const float*)d_in[1];
    const float* rcut   = (const float*)d_in[2];
    const int*   idx_i  = (const int*)d_in[3];
    const int*   idx_j  = (const int*)d_in[4];
    const float* W_in2f = (const float*)d_in[5];
    const float* W_f1   = (const float*)d_in[6];
    const float* b_f1   = (const float*)d_in[7];
    const float* W_f2   = (const float*)d_in[8];
    const float* b_f2   = (const float*)d_in[9];
    const float* W_o1   = (const float*)d_in[10];
    const float* b_o1   = (const float*)d_in[11];
    const float* W_o2   = (const float*)d_in[12];
    const float* b_o2   = (const float*)d_in[13];
    float* out = (float*)d_out;

    const int smemA = (128 * TSTRIDE + 128 * 128) * 4;
    const int smemC = (128 * TSTRIDE + 128 * 128 + 128) * 4;

    cudaFuncSetAttribute(h_kernel, cudaFuncAttributeMaxDynamicSharedMemorySize, smemA);
    cudaFuncSetAttribute(edge_kernel, cudaFuncAttributeMaxDynamicSharedMemorySize, SMEM_EDGE);
    cudaFuncSetAttribute(out_kernel, cudaFuncAttributeMaxDynamicSharedMemorySize, smemC);

    prep_w2_kernel<<<64, 256>>>(W_f2);
    prep_w1_kernel<<<20, 256>>>(W_f1);
    zero_y_kernel<<<512, 256>>>();
    h_kernel<<<(N_ATOMS + 127) / 128, 512, smemA>>>(x, W_in2f);
    edge_kernel<<<N_EDGES / 128, 256, SMEM_EDGE>>>(f_ij, rcut, idx_i, idx_j,
                                                   b_f1, b_f2);
    out_kernel<<<(N_ATOMS + 127) / 128, 512, smemC>>>(W_o1, b_o1, W_o2, b_o2, out);
}